// round 13
// baseline (speedup 1.0000x reference)
#include <cuda_runtime.h>
#include <cuda_fp16.h>
#include <cstdint>

#define BB 8
#define CC 128
#define HH 160
#define WW 512
#define DMAX 64
#define TJ 64
#define THREADS 128

// 16-channel chunks, 4-deep f32 staging ring, padded rows for conflict-free frags
#define SAROW 132                 // A stage row stride (floats), ≡4 mod 32
#define SBROW 68                  // B stage row stride (floats), ≡4 mod 32
#define OFF_FB (16 * SAROW * 4)   // 8448
#define STAGE_BYTES (OFF_FB + 16 * SBROW * 4)   // 12800
#define NRING 4
#define SM_BYTES (NRING * STAGE_BYTES)          // 51200
#define SOUT_STRIDE 68            // 64*68*4 = 17408 B, aliases ring

__device__ __forceinline__ void mma_f16(float* d, const uint32_t* a, const uint32_t* b) {
    asm volatile(
        "mma.sync.aligned.m16n8k16.row.col.f32.f16.f16.f32 "
        "{%0,%1,%2,%3}, {%4,%5,%6,%7}, {%8,%9}, {%0,%1,%2,%3};"
        : "+f"(d[0]), "+f"(d[1]), "+f"(d[2]), "+f"(d[3])
        : "r"(a[0]), "r"(a[1]), "r"(a[2]), "r"(a[3]), "r"(b[0]), "r"(b[1]));
}
__device__ __forceinline__ uint32_t pack2(float lo, float hi) {
    const __half2 h = __floats2half2_rn(lo, hi);
    return *reinterpret_cast<const uint32_t*>(&h);
}
__device__ __forceinline__ void cpa16(uint32_t dst, const float* src) {
    asm volatile("cp.async.cg.shared.global [%0], [%1], 16;" :: "r"(dst), "l"(src));
}

__global__ __launch_bounds__(THREADS, 4)
void cost_volume_kernel(const float* __restrict__ left,
                        const float* __restrict__ right,
                        float* __restrict__ out) {
    extern __shared__ char smem[];
    const uint32_t sbase = (uint32_t)__cvta_generic_to_shared(smem);

    const int tid = threadIdx.x;
    const int wid = tid >> 5;
    const int lid = tid & 31;
    const int gid = lid >> 2;
    const int tig = lid & 3;
    const int j0  = blockIdx.x * TJ;
    const int h   = blockIdx.y;
    const int b   = blockIdx.z;

    const size_t plane = (size_t)HH * WW;
    const float* Lbase = left  + ((size_t)b * CC * HH + h) * WW;
    const float* Rbase = right + ((size_t)b * CC * HH + h) * WW;

    const int kw = wid * 32;    // warp's 32 window rows

    // ---- async stage: 16-channel chunk into ring slot `buf` (padded rows) ----
    auto cp_stage = [&](int chunk, int buf) {
        const int ch0 = chunk * 16;
        const uint32_t base = sbase + buf * STAGE_BYTES;
        #pragma unroll
        for (int i = 0; i < 4; i++) {            // A: 512 granules of 16B
            const int g = tid + 128 * i;
            const int row = g >> 5, c16 = g & 31;
            int gj = j0 - 64 + c16 * 4;
            if (gj < 0) gj = 0;                  // feeds only masked j<d outputs
            cpa16(base + row * (SAROW * 4) + c16 * 16,
                  Rbase + (size_t)(ch0 + row) * plane + gj);
        }
        #pragma unroll
        for (int i = 0; i < 2; i++) {            // B: 256 granules of 16B
            const int g = tid + 128 * i;
            const int row = g >> 4, c16 = g & 15;
            cpa16(base + OFF_FB + row * (SBROW * 4) + c16 * 16,
                  Lbase + (size_t)(ch0 + row) * plane + j0 + c16 * 4);
        }
        asm volatile("cp.async.commit_group;" ::: "memory");
    };

    float acc[2][8][4];
    #pragma unroll
    for (int mt = 0; mt < 2; mt++)
        #pragma unroll
        for (int nt = 0; nt < 8; nt++)
            #pragma unroll
            for (int r = 0; r < 4; r++) acc[mt][nt][r] = 0.0f;

    cp_stage(0, 0); cp_stage(1, 1); cp_stage(2, 2); cp_stage(3, 3);

    int buf = 0;
    for (int c = 0; c < 8; c++) {
        // pending groups allowed once chunk c has landed
        if (c < 5)       asm volatile("cp.async.wait_group 3;" ::: "memory");
        else if (c == 5) asm volatile("cp.async.wait_group 2;" ::: "memory");
        else if (c == 6) asm volatile("cp.async.wait_group 1;" ::: "memory");
        else             asm volatile("cp.async.wait_group 0;" ::: "memory");
        __syncthreads();   // stage(c) visible to all warps

        // ---- compute: fragments packed on the fly from f32 stage ----
        {
            const float* fA = reinterpret_cast<const float*>(smem + buf * STAGE_BYTES);
            const float* fB = reinterpret_cast<const float*>(smem + buf * STAGE_BYTES + OFF_FB);
            const float* a0 = fA + (2 * tig) * SAROW;
            const float* a1 = a0 + SAROW;
            const float* a2 = fA + (2 * tig + 8) * SAROW;
            const float* a3 = a2 + SAROW;
            const float* b0 = fB + (2 * tig) * SBROW;
            const float* b1 = b0 + SBROW;
            const float* b2 = fB + (2 * tig + 8) * SBROW;
            const float* b3 = b2 + SBROW;

            uint32_t af[2][4];
            #pragma unroll
            for (int mt = 0; mt < 2; mt++) {
                const int p = kw + mt * 16 + gid;
                af[mt][0] = pack2(a0[p],     a1[p]);
                af[mt][1] = pack2(a0[p + 8], a1[p + 8]);
                af[mt][2] = pack2(a2[p],     a3[p]);
                af[mt][3] = pack2(a2[p + 8], a3[p + 8]);
            }
            uint32_t bf[8][2];
            #pragma unroll
            for (int nt = 0; nt < 8; nt++) {
                const int jl = nt * 8 + gid;
                bf[nt][0] = pack2(b0[jl], b1[jl]);
                bf[nt][1] = pack2(b2[jl], b3[jl]);
            }
            #pragma unroll
            for (int mt = 0; mt < 2; mt++)
                #pragma unroll
                for (int nt = 0; nt < 8; nt++)
                    mma_f16(acc[mt][nt], af[mt], bf[nt]);
        }
        __syncthreads();   // all warps done reading slot before refill

        if (c + NRING < 8) cp_stage(c + NRING, buf);   // refill; 4 groups in flight

        buf = (buf == NRING - 1) ? 0 : buf + 1;
    }

    // ---- epilogue: band extract -> smem alias -> coalesced store ----
    __syncthreads();
    {
        const float inv = 1.0f / (float)CC;
        float* sOut = reinterpret_cast<float*>(smem);
        #pragma unroll
        for (int mt = 0; mt < 2; mt++) {
            const int k0t = kw + mt * 16 + gid;
            #pragma unroll
            for (int nt = 0; nt < 8; nt++) {
                const int jj0t = nt * 8 + 2 * tig;
                #pragma unroll
                for (int r = 0; r < 4; r++) {
                    const int kk = k0t + ((r >= 2) ? 8 : 0);
                    const int jx = jj0t + (r & 1);
                    const int d  = jx + 64 - kk;
                    if (d >= 0 && d < 64) {
                        const int j = j0 + jx;
                        sOut[d * SOUT_STRIDE + jx] = (j >= d) ? acc[mt][nt][r] * inv : 0.0f;
                    }
                }
            }
        }
    }
    __syncthreads();
    {
        const float* sOut = reinterpret_cast<const float*>(smem);
        float* obase = out + ((size_t)b * DMAX * HH + h) * WW + j0;
        #pragma unroll
        for (int it = 0; it < 8; it++) {
            const int idx = it * THREADS + tid;
            const int d  = idx >> 4;
            const int qq = idx & 15;
            const float4 v = *reinterpret_cast<const float4*>(sOut + d * SOUT_STRIDE + 4 * qq);
            *reinterpret_cast<float4*>(obase + (size_t)d * plane + 4 * qq) = v;
        }
    }
}

extern "C" void kernel_launch(void* const* d_in, const int* in_sizes, int n_in,
                              void* d_out, int out_size) {
    const float* left  = (const float*)d_in[0];
    const float* right = (const float*)d_in[1];
    float* out = (float*)d_out;

    cudaFuncSetAttribute(cost_volume_kernel,
                         cudaFuncAttributeMaxDynamicSharedMemorySize, SM_BYTES);

    dim3 grid(WW / TJ, HH, BB);
    cost_volume_kernel<<<grid, THREADS, SM_BYTES>>>(left, right, out);
}

// round 14
// speedup vs baseline: 1.5365x; 1.5365x over previous
#include <cuda_runtime.h>
#include <cuda_fp16.h>
#include <cstdint>

#define BB 8
#define CC 128
#define HH 160
#define WW 512
#define DMAX 64
#define TJ 64
#define THREADS 128

// 16-channel chunks, 4-deep f32 staging ring
#define STAGE_BYTES 12288        // A: 16x128x4 = 8192, B: 16x64x4 = 4096
#define OFF_FB_IN_STAGE 8192
#define NRING 4
#define OFF_H  (NRING * STAGE_BYTES)         // 49152
#define SJ2 136                  // f16 A tile row stride (half2 units)
#define SJB2 72                  // f16 B tile row stride (half2 units)
#define OFF_HA OFF_H
#define OFF_HB (OFF_H + 8 * SJ2 * 4)         // 53504
#define SM_BYTES (OFF_HB + 8 * SJB2 * 4)     // 55808
#define SOUT_STRIDE 68           // 64*68*4 = 17408 B, aliases staging ring

__device__ __forceinline__ void mma_f16(float* d, const uint32_t* a, const uint32_t* b) {
    asm volatile(
        "mma.sync.aligned.m16n8k16.row.col.f32.f16.f16.f32 "
        "{%0,%1,%2,%3}, {%4,%5,%6,%7}, {%8,%9}, {%0,%1,%2,%3};"
        : "+f"(d[0]), "+f"(d[1]), "+f"(d[2]), "+f"(d[3])
        : "r"(a[0]), "r"(a[1]), "r"(a[2]), "r"(a[3]), "r"(b[0]), "r"(b[1]));
}
__device__ __forceinline__ uint32_t pack2(float lo, float hi) {
    const __half2 h = __floats2half2_rn(lo, hi);
    return *reinterpret_cast<const uint32_t*>(&h);
}
__device__ __forceinline__ void cpa16(uint32_t dst, const float* src) {
    asm volatile("cp.async.cg.shared.global [%0], [%1], 16;" :: "r"(dst), "l"(src));
}

__global__ __launch_bounds__(THREADS, 4)
void cost_volume_kernel(const float* __restrict__ left,
                        const float* __restrict__ right,
                        float* __restrict__ out) {
    extern __shared__ char smem[];
    const uint32_t sbase = (uint32_t)__cvta_generic_to_shared(smem);

    const int tid = threadIdx.x;
    const int wid = tid >> 5;
    const int lid = tid & 31;
    const int gid = lid >> 2;
    const int tig = lid & 3;
    const int j0  = blockIdx.x * TJ;
    const int h   = blockIdx.y;
    const int b   = blockIdx.z;

    const size_t plane = (size_t)HH * WW;
    const float* Lbase = left  + ((size_t)b * CC * HH + h) * WW;
    const float* Rbase = right + ((size_t)b * CC * HH + h) * WW;

    const int kw = wid * 32;    // warp's 32 window rows

    // hoisted staging thread-map pieces
    const int aRow = tid >> 5, aC16 = tid & 31;       // A granule coords (+128/iter)
    const int bRow = tid >> 4, bC16 = tid & 15;       // B granule coords (+128/iter)
    int gjA = j0 - 64 + aC16 * 4;
    if (gjA < 0) gjA = 0;                             // feeds only masked j<d outputs

    // ---- async stage: 16-channel chunk into ring slot `buf` ----
    auto cp_stage = [&](int chunk, int buf) {
        const int ch0 = chunk * 16;
        const uint32_t base = sbase + buf * STAGE_BYTES;
        #pragma unroll
        for (int i = 0; i < 4; i++) {            // A: 512 granules of 16B
            const int row = aRow + 4 * i;
            cpa16(base + row * 512 + aC16 * 16,
                  Rbase + (size_t)(ch0 + row) * plane + gjA);
        }
        #pragma unroll
        for (int i = 0; i < 2; i++) {            // B: 256 granules of 16B
            const int row = bRow + 8 * i;
            cpa16(base + OFF_FB_IN_STAGE + row * 256 + bC16 * 16,
                  Lbase + (size_t)(ch0 + row) * plane + j0 + bC16 * 4);
        }
        asm volatile("cp.async.commit_group;" ::: "memory");
    };

    float acc[2][8][4];
    #pragma unroll
    for (int mt = 0; mt < 2; mt++)
        #pragma unroll
        for (int nt = 0; nt < 8; nt++)
            #pragma unroll
            for (int r = 0; r < 4; r++) acc[mt][nt][r] = 0.0f;

    cp_stage(0, 0); cp_stage(1, 1); cp_stage(2, 2); cp_stage(3, 3);

    // hoisted fragment base pointers (compile-time tile offsets)
    const uint32_t* hA  = reinterpret_cast<const uint32_t*>(smem + OFF_HA);
    const uint32_t* hB  = reinterpret_cast<const uint32_t*>(smem + OFF_HB);
    const uint32_t* As  = hA + tig * SJ2;
    const uint32_t* As4 = As + 4 * SJ2;
    const uint32_t* Bs  = hB + tig * SJB2;
    const uint32_t* Bs4 = Bs + 4 * SJB2;

    #pragma unroll
    for (int c = 0; c < 8; c++) {
        const int buf = c & 3;
        // chunk c complete when at most min(3, 7-c) groups remain pending
        if (c < 5)       asm volatile("cp.async.wait_group 3;" ::: "memory");
        else if (c == 5) asm volatile("cp.async.wait_group 2;" ::: "memory");
        else if (c == 6) asm volatile("cp.async.wait_group 1;" ::: "memory");
        else             asm volatile("cp.async.wait_group 0;" ::: "memory");
        __syncthreads();   // stage(c) ready; all warps done with f16 tiles of c-1

        // ---- convert: f32 stage -> packed half2 tiles ----
        {
            const float* fA = reinterpret_cast<const float*>(smem + buf * STAGE_BYTES);
            const float* fB = reinterpret_cast<const float*>(smem + buf * STAGE_BYTES + OFF_FB_IN_STAGE);
            uint32_t* wA = reinterpret_cast<uint32_t*>(smem + OFF_HA);
            uint32_t* wB = reinterpret_cast<uint32_t*>(smem + OFF_HB);
            #pragma unroll
            for (int i = 0; i < 2; i++) {        // A: 256 uint4 tasks
                const int g = tid + 128 * i;
                const int c2 = g >> 5, q4 = g & 31;
                const float4 e = *reinterpret_cast<const float4*>(fA + (2 * c2) * 128 + q4 * 4);
                const float4 o = *reinterpret_cast<const float4*>(fA + (2 * c2 + 1) * 128 + q4 * 4);
                uint4 w;
                w.x = pack2(e.x, o.x); w.y = pack2(e.y, o.y);
                w.z = pack2(e.z, o.z); w.w = pack2(e.w, o.w);
                *reinterpret_cast<uint4*>(wA + c2 * SJ2 + q4 * 4) = w;
            }
            {                                     // B: 128 uint4 tasks
                const int c2 = tid >> 4, q4 = tid & 15;
                const float4 e = *reinterpret_cast<const float4*>(fB + (2 * c2) * 64 + q4 * 4);
                const float4 o = *reinterpret_cast<const float4*>(fB + (2 * c2 + 1) * 64 + q4 * 4);
                uint4 w;
                w.x = pack2(e.x, o.x); w.y = pack2(e.y, o.y);
                w.z = pack2(e.z, o.z); w.w = pack2(e.w, o.w);
                *reinterpret_cast<uint4*>(wB + c2 * SJB2 + q4 * 4) = w;
            }
        }
        __syncthreads();   // stage slot free, f16 tiles visible

        if (c + NRING < 8) cp_stage(c + NRING, buf);   // refill; 4 groups in flight

        // ---- compute: one k16 step ----
        {
            uint32_t af[2][4];
            #pragma unroll
            for (int mt = 0; mt < 2; mt++) {
                const int p = kw + mt * 16 + gid;
                af[mt][0] = As[p];   af[mt][1] = As[p + 8];
                af[mt][2] = As4[p];  af[mt][3] = As4[p + 8];
            }
            uint32_t bf[8][2];
            #pragma unroll
            for (int nt = 0; nt < 8; nt++) {
                const int jl = nt * 8 + gid;
                bf[nt][0] = Bs[jl];  bf[nt][1] = Bs4[jl];
            }
            #pragma unroll
            for (int mt = 0; mt < 2; mt++)
                #pragma unroll
                for (int nt = 0; nt < 8; nt++)
                    mma_f16(acc[mt][nt], af[mt], bf[nt]);
        }
    }

    // ---- epilogue: band extract -> smem alias -> coalesced store ----
    __syncthreads();
    {
        const float inv = 1.0f / (float)CC;
        float* sOut = reinterpret_cast<float*>(smem);
        #pragma unroll
        for (int mt = 0; mt < 2; mt++) {
            const int k0t = kw + mt * 16 + gid;
            #pragma unroll
            for (int nt = 0; nt < 8; nt++) {
                const int jj0t = nt * 8 + 2 * tig;
                #pragma unroll
                for (int r = 0; r < 4; r++) {
                    const int kk = k0t + ((r >= 2) ? 8 : 0);
                    const int jx = jj0t + (r & 1);
                    const int d  = jx + 64 - kk;
                    if (d >= 0 && d < 64) {
                        const int j = j0 + jx;
                        sOut[d * SOUT_STRIDE + jx] = (j >= d) ? acc[mt][nt][r] * inv : 0.0f;
                    }
                }
            }
        }
    }
    __syncthreads();
    {
        const float* sOut = reinterpret_cast<const float*>(smem);
        float* obase = out + ((size_t)b * DMAX * HH + h) * WW + j0;
        #pragma unroll
        for (int it = 0; it < 8; it++) {
            const int idx = it * THREADS + tid;
            const int d  = idx >> 4;
            const int qq = idx & 15;
            const float4 v = *reinterpret_cast<const float4*>(sOut + d * SOUT_STRIDE + 4 * qq);
            *reinterpret_cast<float4*>(obase + (size_t)d * plane + 4 * qq) = v;
        }
    }
}

extern "C" void kernel_launch(void* const* d_in, const int* in_sizes, int n_in,
                              void* d_out, int out_size) {
    const float* left  = (const float*)d_in[0];
    const float* right = (const float*)d_in[1];
    float* out = (float*)d_out;

    cudaFuncSetAttribute(cost_volume_kernel,
                         cudaFuncAttributeMaxDynamicSharedMemorySize, SM_BYTES);

    dim3 grid(WW / TJ, HH, BB);
    cost_volume_kernel<<<grid, THREADS, SM_BYTES>>>(left, right, out);
}

// round 15
// speedup vs baseline: 1.6241x; 1.0570x over previous
#include <cuda_runtime.h>
#include <cuda_fp16.h>
#include <cstdint>

#define BB 8
#define CC 128
#define HH 160
#define WW 512
#define DMAX 64
#define TJ 64
#define THREADS 128

// 16-channel chunks, 4-deep f32 staging ring
#define STAGE_BYTES 12288        // A: 16x128x4 = 8192, B: 16x64x4 = 4096
#define OFF_FB_IN_STAGE 8192
#define NRING 4
#define OFF_H  (NRING * STAGE_BYTES)         // 49152
#define SJ2 136                  // f16 A tile row stride (half2 units)
#define SJB2 72                  // f16 B tile row stride (half2 units)
#define OFF_HA OFF_H
#define OFF_HB (OFF_H + 8 * SJ2 * 4)         // 53504
#define SM_BYTES (OFF_HB + 8 * SJB2 * 4)     // 55808
#define SOUT_STRIDE 68           // 64*68*4 = 17408 B, aliases staging ring

__device__ __forceinline__ void mma_f16(float* d, const uint32_t* a, const uint32_t* b) {
    asm volatile(
        "mma.sync.aligned.m16n8k16.row.col.f32.f16.f16.f32 "
        "{%0,%1,%2,%3}, {%4,%5,%6,%7}, {%8,%9}, {%0,%1,%2,%3};"
        : "+f"(d[0]), "+f"(d[1]), "+f"(d[2]), "+f"(d[3])
        : "r"(a[0]), "r"(a[1]), "r"(a[2]), "r"(a[3]), "r"(b[0]), "r"(b[1]));
}
__device__ __forceinline__ uint32_t pack2(float lo, float hi) {
    const __half2 h = __floats2half2_rn(lo, hi);
    return *reinterpret_cast<const uint32_t*>(&h);
}
__device__ __forceinline__ void cpa16(uint32_t dst, const float* src) {
    asm volatile("cp.async.cg.shared.global [%0], [%1], 16;" :: "r"(dst), "l"(src));
}
__device__ __forceinline__ void stcs4(float* p, float4 v) {
    asm volatile("st.global.cs.v4.f32 [%0], {%1, %2, %3, %4};"
                 :: "l"(p), "f"(v.x), "f"(v.y), "f"(v.z), "f"(v.w) : "memory");
}

__global__ __launch_bounds__(THREADS, 4)
void cost_volume_kernel(const float* __restrict__ left,
                        const float* __restrict__ right,
                        float* __restrict__ out) {
    extern __shared__ char smem[];
    const uint32_t sbase = (uint32_t)__cvta_generic_to_shared(smem);

    const int tid = threadIdx.x;
    const int wid = tid >> 5;
    const int lid = tid & 31;
    const int gid = lid >> 2;
    const int tig = lid & 3;
    const int j0  = blockIdx.x * TJ;
    const int h   = blockIdx.y;
    const int b   = blockIdx.z;

    const size_t plane = (size_t)HH * WW;
    const float* Lbase = left  + ((size_t)b * CC * HH + h) * WW;
    const float* Rbase = right + ((size_t)b * CC * HH + h) * WW;

    const int kw = wid * 32;    // warp's 32 window rows

    // ---- async stage: 16-channel chunk into ring slot `buf` ----
    auto cp_stage = [&](int chunk, int buf) {
        const int ch0 = chunk * 16;
        const uint32_t base = sbase + buf * STAGE_BYTES;
        #pragma unroll
        for (int i = 0; i < 4; i++) {            // A: 512 granules of 16B
            const int g = tid + 128 * i;
            const int row = g >> 5, c16 = g & 31;
            int gj = j0 - 64 + c16 * 4;
            if (gj < 0) gj = 0;                  // feeds only masked j<d outputs
            cpa16(base + row * 512 + c16 * 16,
                  Rbase + (size_t)(ch0 + row) * plane + gj);
        }
        #pragma unroll
        for (int i = 0; i < 2; i++) {            // B: 256 granules of 16B
            const int g = tid + 128 * i;
            const int row = g >> 4, c16 = g & 15;
            cpa16(base + OFF_FB_IN_STAGE + row * 256 + c16 * 16,
                  Lbase + (size_t)(ch0 + row) * plane + j0 + c16 * 4);
        }
        asm volatile("cp.async.commit_group;" ::: "memory");
    };

    float acc[2][8][4];
    #pragma unroll
    for (int mt = 0; mt < 2; mt++)
        #pragma unroll
        for (int nt = 0; nt < 8; nt++)
            #pragma unroll
            for (int r = 0; r < 4; r++) acc[mt][nt][r] = 0.0f;

    cp_stage(0, 0); cp_stage(1, 1); cp_stage(2, 2); cp_stage(3, 3);

    int buf = 0;
    for (int c = 0; c < 8; c++) {
        // chunk c complete when at most min(3, 7-c) groups remain pending
        if (c < 5)       asm volatile("cp.async.wait_group 3;" ::: "memory");
        else if (c == 5) asm volatile("cp.async.wait_group 2;" ::: "memory");
        else if (c == 6) asm volatile("cp.async.wait_group 1;" ::: "memory");
        else             asm volatile("cp.async.wait_group 0;" ::: "memory");
        __syncthreads();   // stage(c) ready; all warps done with f16 tiles of c-1

        // ---- convert: f32 stage -> packed half2 tiles ----
        {
            const float* fA = reinterpret_cast<const float*>(smem + buf * STAGE_BYTES);
            const float* fB = reinterpret_cast<const float*>(smem + buf * STAGE_BYTES + OFF_FB_IN_STAGE);
            uint32_t* hA = reinterpret_cast<uint32_t*>(smem + OFF_HA);
            uint32_t* hB = reinterpret_cast<uint32_t*>(smem + OFF_HB);
            #pragma unroll
            for (int i = 0; i < 2; i++) {        // A: 256 uint4 tasks
                const int g = tid + 128 * i;
                const int c2 = g >> 5, q4 = g & 31;
                const float4 e = *reinterpret_cast<const float4*>(fA + (2 * c2) * 128 + q4 * 4);
                const float4 o = *reinterpret_cast<const float4*>(fA + (2 * c2 + 1) * 128 + q4 * 4);
                uint4 w;
                w.x = pack2(e.x, o.x); w.y = pack2(e.y, o.y);
                w.z = pack2(e.z, o.z); w.w = pack2(e.w, o.w);
                *reinterpret_cast<uint4*>(hA + c2 * SJ2 + q4 * 4) = w;
            }
            {                                     // B: 128 uint4 tasks
                const int c2 = tid >> 4, q4 = tid & 15;
                const float4 e = *reinterpret_cast<const float4*>(fB + (2 * c2) * 64 + q4 * 4);
                const float4 o = *reinterpret_cast<const float4*>(fB + (2 * c2 + 1) * 64 + q4 * 4);
                uint4 w;
                w.x = pack2(e.x, o.x); w.y = pack2(e.y, o.y);
                w.z = pack2(e.z, o.z); w.w = pack2(e.w, o.w);
                *reinterpret_cast<uint4*>(hB + c2 * SJB2 + q4 * 4) = w;
            }
        }
        __syncthreads();   // stage slot free, f16 tiles visible

        if (c + NRING < 8) cp_stage(c + NRING, buf);   // refill; 4 groups in flight

        // ---- compute: one k16 step ----
        {
            const uint32_t* As  = reinterpret_cast<const uint32_t*>(smem + OFF_HA) + tig * SJ2;
            const uint32_t* As4 = As + 4 * SJ2;
            const uint32_t* Bs  = reinterpret_cast<const uint32_t*>(smem + OFF_HB) + tig * SJB2;
            const uint32_t* Bs4 = Bs + 4 * SJB2;

            uint32_t af[2][4];
            #pragma unroll
            for (int mt = 0; mt < 2; mt++) {
                const int p = kw + mt * 16 + gid;
                af[mt][0] = As[p];   af[mt][1] = As[p + 8];
                af[mt][2] = As4[p];  af[mt][3] = As4[p + 8];
            }
            uint32_t bf[8][2];
            #pragma unroll
            for (int nt = 0; nt < 8; nt++) {
                const int jl = nt * 8 + gid;
                bf[nt][0] = Bs[jl];  bf[nt][1] = Bs4[jl];
            }
            #pragma unroll
            for (int mt = 0; mt < 2; mt++)
                #pragma unroll
                for (int nt = 0; nt < 8; nt++)
                    mma_f16(acc[mt][nt], af[mt], bf[nt]);
        }

        buf = (buf == NRING - 1) ? 0 : buf + 1;
    }

    // ---- epilogue: band extract -> smem alias -> coalesced streaming store ----
    __syncthreads();
    {
        const float inv = 1.0f / (float)CC;
        float* sOut = reinterpret_cast<float*>(smem);
        #pragma unroll
        for (int mt = 0; mt < 2; mt++) {
            const int k0t = kw + mt * 16 + gid;
            #pragma unroll
            for (int nt = 0; nt < 8; nt++) {
                const int jj0t = nt * 8 + 2 * tig;
                #pragma unroll
                for (int r = 0; r < 4; r++) {
                    const int kk = k0t + ((r >= 2) ? 8 : 0);
                    const int jx = jj0t + (r & 1);
                    const int d  = jx + 64 - kk;
                    if (d >= 0 && d < 64) {
                        const int j = j0 + jx;
                        sOut[d * SOUT_STRIDE + jx] = (j >= d) ? acc[mt][nt][r] * inv : 0.0f;
                    }
                }
            }
        }
    }
    __syncthreads();
    {
        const float* sOut = reinterpret_cast<const float*>(smem);
        float* obase = out + ((size_t)b * DMAX * HH + h) * WW + j0;
        #pragma unroll
        for (int it = 0; it < 8; it++) {
            const int idx = it * THREADS + tid;
            const int d  = idx >> 4;
            const int qq = idx & 15;
            const float4 v = *reinterpret_cast<const float4*>(sOut + d * SOUT_STRIDE + 4 * qq);
            stcs4(obase + (size_t)d * plane + 4 * qq, v);
        }
    }
}

extern "C" void kernel_launch(void* const* d_in, const int* in_sizes, int n_in,
                              void* d_out, int out_size) {
    const float* left  = (const float*)d_in[0];
    const float* right = (const float*)d_in[1];
    float* out = (float*)d_out;

    cudaFuncSetAttribute(cost_volume_kernel,
                         cudaFuncAttributeMaxDynamicSharedMemorySize, SM_BYTES);

    dim3 grid(WW / TJ, HH, BB);
    cost_volume_kernel<<<grid, THREADS, SM_BYTES>>>(left, right, out);
}